// round 12
// baseline (speedup 1.0000x reference)
#include <cuda_runtime.h>
#include <cstdint>

#define MARGIN 0.3f
#define EPSV   1e-6f

#define MAX_B 8192
#define MAX_L 1024
#define UINF  0xFFFFFFFFu

// Single memset-able region (0xFF -> all UINF).
struct OccTab {
    unsigned m1[MAX_L];   // first-occurrence index per label
    unsigned m2[MAX_L];   // second-occurrence index per label
    unsigned diff;        // first index with label != label[0]
};
__device__ OccTab g_occ;
__device__ int    g_lab32[MAX_B];        // decoded int32 labels
__device__ float2 g_part[MAX_B/16 + 1];  // per-block {loss_sum, valid_cnt}

// two-min insert: whoever loses the m1 comparison feeds m2; the true min
// never loses, so m2 converges to the second-smallest inserted value.
__device__ __forceinline__ void twomin_insert(unsigned* m1, unsigned* m2, unsigned v) {
    unsigned old = atomicMin(m1, v);
    if (old != UINF) atomicMin(m2, (v < old) ? old : v);
}

// ================================================================ kernel A
// Partitioned occurrence pass: per-block smem two-min tables, global merge.
__global__ void k_occ_part(const void* __restrict__ labels, int B) {
    __shared__ unsigned s_m1[MAX_L];
    __shared__ unsigned s_m2[MAX_L];
    __shared__ unsigned s_diff;
    int t = threadIdx.x;
    int nt = blockDim.x;
    int lane = t & 31;

    for (int j = t; j < MAX_L; j += nt) { s_m1[j] = UINF; s_m2[j] = UINF; }
    if (t == 0) s_diff = UINF;

    // dtype detect (full range, redundant per block -> globally consistent).
    // Odd 32-bit words < B are high halves of int64 labels (zero when
    // labels < 2^32) or independent int32 labels (never all zero).
    const int* w = (const int*)labels;
    int any = 0;
    for (int i = 2 * t + 1; i < B; i += 2 * nt) any |= w[i];
    int is64 = (__syncthreads_or(any) == 0);   // also orders smem init

    int l0 = is64 ? (int)((const long long*)labels)[0] : w[0];

    // this block's slice
    int slice = (B + gridDim.x - 1) / gridDim.x;
    int base  = blockIdx.x * slice;
    int end   = min(base + slice, B);

    unsigned cand = UINF;
    for (int i = base + t; i < end; i += nt) {
        int lab = is64 ? (int)((const long long*)labels)[i] : w[i];
        g_lab32[i] = lab;
        if ((unsigned)lab < MAX_L)
            twomin_insert(&s_m1[lab], &s_m2[lab], (unsigned)i);
        if (lab != l0 && (unsigned)i < cand) cand = (unsigned)i;
    }

    #pragma unroll
    for (int off = 16; off > 0; off >>= 1)
        cand = min(cand, __shfl_down_sync(0xffffffffu, cand, off));
    if (lane == 0 && cand != UINF) atomicMin(&s_diff, cand);
    __syncthreads();

    // merge live local entries into the global table (spread, one wave)
    for (int j = t; j < MAX_L; j += nt) {
        unsigned v1 = s_m1[j];
        if (v1 != UINF) {
            twomin_insert(&g_occ.m1[j], &g_occ.m2[j], v1);
            unsigned v2 = s_m2[j];
            if (v2 != UINF) twomin_insert(&g_occ.m1[j], &g_occ.m2[j], v2);
        }
    }
    if (t == 0 && s_diff != UINF) atomicMin(&g_occ.diff, s_diff);
}

// ================================================================ kernel B
// Warp per anchor. Negative row 0 staged in smem (it serves ~all anchors),
// cutting the L2-side traffic by ~1/3. Block-partial deterministic sums.
__global__ void k_dist(const float* __restrict__ features, int B, int D) {
    __shared__ float4 s_neg[256];    // feature row 0 (4 KB), D==1024 fast path
    __shared__ float  s_loss[16];
    __shared__ int    s_val[16];
    int wib  = threadIdx.x >> 5;
    int warp = blockIdx.x * (blockDim.x >> 5) + wib;
    int lane = threadIdx.x & 31;

    // cooperative stage of feature row 0 into smem
    if (D == 1024 && threadIdx.x < 256)
        s_neg[threadIdx.x] = ((const float4*)features)[threadIdx.x];
    __syncthreads();

    float my_loss = 0.0f;
    int   my_val  = 0;

    if (warp < B) {
        int lab = g_lab32[warp];
        unsigned p = UINF, n = UINF;
        if ((unsigned)lab < MAX_L) {
            unsigned m1 = __ldcg(&g_occ.m1[lab]);
            p = (m1 == (unsigned)warp) ? __ldcg(&g_occ.m2[lab]) : m1;
            n = (lab != g_lab32[0]) ? 0u : __ldcg(&g_occ.diff);
        }
        if (p != UINF && n != UINF) {
            const float4* __restrict__ A = (const float4*)(features + (size_t)warp * D);
            const float4* __restrict__ P = (const float4*)(features + (size_t)p * D);
            float sap = 0.0f, san = 0.0f;

            if (D == 1024) {
                // negative source: smem for n==0 (the common case), else global
                const float4* N = (n == 0u) ? s_neg
                                            : (const float4*)(features + (size_t)n * D);
                float4 a  = __ldcs(&A[lane]);    // anchor: streaming (read-once)
                float4 pp = P[lane];
                float4 nn = N[lane];
                #pragma unroll
                for (int k = 1; k <= 8; k++) {
                    float4 a2, p2, n2;
                    if (k < 8) {
                        a2 = __ldcs(&A[lane + 32 * k]);
                        p2 = P[lane + 32 * k];
                        n2 = N[lane + 32 * k];
                    }
                    float d;
                    d = a.x - pp.x + EPSV; sap = fmaf(d, d, sap);
                    d = a.y - pp.y + EPSV; sap = fmaf(d, d, sap);
                    d = a.z - pp.z + EPSV; sap = fmaf(d, d, sap);
                    d = a.w - pp.w + EPSV; sap = fmaf(d, d, sap);
                    d = a.x - nn.x + EPSV; san = fmaf(d, d, san);
                    d = a.y - nn.y + EPSV; san = fmaf(d, d, san);
                    d = a.z - nn.z + EPSV; san = fmaf(d, d, san);
                    d = a.w - nn.w + EPSV; san = fmaf(d, d, san);
                    a = a2; pp = p2; nn = n2;
                }
            } else {
                const float4* __restrict__ N = (const float4*)(features + (size_t)n * D);
                int nv = D >> 2;
                for (int k = lane; k < nv; k += 32) {
                    float4 a = A[k], pp = P[k], nn = N[k];
                    float d;
                    d = a.x - pp.x + EPSV; sap = fmaf(d, d, sap);
                    d = a.y - pp.y + EPSV; sap = fmaf(d, d, sap);
                    d = a.z - pp.z + EPSV; sap = fmaf(d, d, sap);
                    d = a.w - pp.w + EPSV; sap = fmaf(d, d, sap);
                    d = a.x - nn.x + EPSV; san = fmaf(d, d, san);
                    d = a.y - nn.y + EPSV; san = fmaf(d, d, san);
                    d = a.z - nn.z + EPSV; san = fmaf(d, d, san);
                    d = a.w - nn.w + EPSV; san = fmaf(d, d, san);
                }
            }
            #pragma unroll
            for (int off = 16; off > 0; off >>= 1) {
                sap += __shfl_down_sync(0xffffffffu, sap, off);
                san += __shfl_down_sync(0xffffffffu, san, off);
            }
            my_loss = fmaxf(sqrtf(sap) - sqrtf(san) + MARGIN, 0.0f);
            my_val  = 1;
        }
    }

    // block-partial reduction (fixed order -> deterministic)
    if (lane == 0) { s_loss[wib] = my_loss; s_val[wib] = my_val; }
    __syncthreads();
    if (threadIdx.x == 0) {
        float sum = 0.0f; int cnt = 0;
        #pragma unroll
        for (int j = 0; j < 16; j++) { sum += s_loss[j]; cnt += s_val[j]; }
        g_part[blockIdx.x] = make_float2(sum, (float)cnt);
    }
}

// ================================================================ kernel C
// Deterministic single-block reduction over block partials.
__global__ void k_reduce(float* __restrict__ out, int npart) {
    __shared__ float s_sum[512];
    __shared__ float s_cnt[512];
    int t = threadIdx.x;
    float sum = 0.0f, cnt = 0.0f;
    for (int i = t; i < npart; i += blockDim.x) {
        float2 v = g_part[i];
        sum += v.x; cnt += v.y;
    }
    s_sum[t] = sum;
    s_cnt[t] = cnt;
    __syncthreads();
    for (int off = (int)blockDim.x >> 1; off > 0; off >>= 1) {
        if (t < off) {
            s_sum[t] += s_sum[t + off];
            s_cnt[t] += s_cnt[t + off];
        }
        __syncthreads();
    }
    if (t == 0)
        out[0] = (s_cnt[0] > 0.0f) ? (s_sum[0] / s_cnt[0]) : 0.0f;
}

// ================================================================ launch
extern "C" void kernel_launch(void* const* d_in, const int* in_sizes, int n_in,
                              void* d_out, int out_size) {
    int i_feat = (in_sizes[0] >= in_sizes[1]) ? 0 : 1;
    int i_lab  = 1 - i_feat;
    const float* features = (const float*)d_in[i_feat];
    const void*  labels   = d_in[i_lab];
    int B = in_sizes[i_lab];
    int D = in_sizes[i_feat] / B;

    void* occ_ptr = nullptr;
    cudaGetSymbolAddress(&occ_ptr, g_occ);              // address query, no alloc
    cudaMemsetAsync(occ_ptr, 0xFF, sizeof(OccTab));     // m1/m2/diff -> UINF

    int nocc = min(8, (B + 1023) / 1024);               // 8 SMs share atomic work
    int nblk = (B + 15) / 16;                           // 16 anchors per 512-thr block
    k_occ_part<<<nocc, 1024>>>(labels, B);
    k_dist    <<<nblk, 512>>>(features, B, D);
    k_reduce  <<<1, 512>>>((float*)d_out, nblk);
}